// round 13
// baseline (speedup 1.0000x reference)
#include <cuda_runtime.h>

#define BN   8
#define NP   2048
#define DETK 100
#define NT   1024
#define WIN  128
#define FULL 0xffffffffu

typedef unsigned long long ull;

// Inter-kernel scratch (allocation-free: __device__ globals)
__device__ ull    g_keys[BN * NP];
__device__ float4 g_box [BN * NP];

static __device__ __forceinline__ float stable_sigmoid(float d) {
    return (d >= 0.0f) ? (1.0f / (1.0f + expf(-d)))
                       : (expf(d) / (1.0f + expf(d)));
}
static __device__ __forceinline__ unsigned f2s(float f) {
    unsigned u = __float_as_uint(f);
    return (u & 0x80000000u) ? ~u : (u | 0x80000000u);
}
static __device__ __forceinline__ float s2f(unsigned u) {
    u = (u & 0x80000000u) ? (u & 0x7FFFFFFFu) : ~u;
    return __uint_as_float(u);
}

// ---------------- Kernel 1: decode half-image + sort its 1024 keys (unchanged R11) ----------------
__global__ __launch_bounds__(NT, 1)
void k1_decode_sort(const float* __restrict__ clss,
                    const float* __restrict__ regs,
                    const float* __restrict__ qlts,
                    const float* __restrict__ props)
{
    __shared__ ull kb[2][NT];

    const int b    = blockIdx.x >> 1;
    const int h    = blockIdx.x & 1;
    const int tid  = threadIdx.x;
    const int lane = tid & 31;
    const int g    = (h << 10) | tid;

    const float W_IMG = 1344.0f, H_IMG = 800.0f;
    const float CLIPV = 4.135166556742356f;   // log(1000/16)

    const float2* cls = (const float2*)(clss  + (size_t)b * NP * 2);
    const float4* reg = (const float4*)(regs  + (size_t)b * NP * 4);
    const float*  qlt =                 qlts  + (size_t)b * NP;
    const float4* prp = (const float4*)(props + (size_t)b * NP * 4);

    float4 p = prp[g];
    float bw = p.z - p.x, bh = p.w - p.y;
    float cx = p.x + 0.5f * bw, cy = p.y + 0.5f * bh;

    float4 r = reg[g];
    float dx = r.x * 0.1f;
    float dy = r.y * 0.1f;
    float dw = fminf(r.z * 0.2f, CLIPV);
    float dh = fminf(r.w * 0.2f, CLIPV);

    float pcx = dx * bw + cx;
    float pcy = dy * bh + cy;
    float pw  = expf(dw) * bw;
    float ph  = expf(dh) * bh;

    float x1 = fminf(fmaxf(pcx - 0.5f * pw, 0.0f), W_IMG);
    float y1 = fminf(fmaxf(pcy - 0.5f * ph, 0.0f), H_IMG);
    float x2 = fminf(fmaxf(pcx + 0.5f * pw, 0.0f), W_IMG);
    float y2 = fminf(fmaxf(pcy + 0.5f * ph, 0.0f), H_IMG);

    bool small_keep = ((x2 - x1) >= 0.01f) && ((y2 - y1) >= 0.01f);

    float2 c = cls[g];
    float raw = stable_sigmoid(c.y - c.x);
    bool  score_keep = raw > 0.5f;
    float score = stable_sigmoid(qlt[g]) * raw;

    bool valid = small_keep && score_keep;
    unsigned k32 = valid ? f2s(score) : 0u;   // valid <=> k32 >= 0x80000000

    g_box[b * NP + g] = make_float4(x1, y1, x2, y2);
    ull key = ((ull)k32 << 32) | (unsigned)(NP - 1 - g);

    // half-sort: direction from GLOBAL index g (half0 desc, half1 asc)
    int cur = 0;
    #pragma unroll
    for (int k = 2; k <= 1024; k <<= 1) {
        #pragma unroll
        for (int jj = k >> 1; jj > 0; jj >>= 1) {
            if (jj >= 32) {
                kb[cur][tid] = key;
                __syncthreads();
                ull pk = kb[cur][tid ^ jj];
                bool tm = ((g & k) == 0) != ((tid & jj) != 0);
                key = tm ? (key > pk ? key : pk) : (key < pk ? key : pk);
                cur ^= 1;
            } else {
                ull pk = __shfl_xor_sync(FULL, key, jj);
                bool tm = ((g & k) == 0) != ((lane & jj) != 0);
                key = tm ? (key > pk ? key : pk) : (key < pk ? key : pk);
            }
        }
    }
    g_keys[b * NP + g] = key;
}

// ---------------- Kernel 2: merge + parallel-B2 mask NMS + output ----------------
struct Smem2 {
    ull      kbuf[2][NP];            // merge exchange buffers (32 KB)
    float4   wbox[WIN];
    float    warea[WIN];
    unsigned wkey[WIN];
    alignas(16) unsigned mask[WIN][4];
    int      okarr[WIN];
    unsigned alive[4];
    float4   kbox[DETK];
    float    karea[DETK];
    unsigned keepkey[DETK];
    int      keepwin[DETK];
    int      cnt;
    int      stop;
};

__global__ __launch_bounds__(NT, 1)
void k2_merge_nms(float* __restrict__ out)
{
    __shared__ Smem2 sm;

    const int b    = blockIdx.x;
    const int tid  = threadIdx.x;
    const int lane = tid & 31;

    ull e0 = g_keys[b * NP + tid];
    ull e1 = g_keys[b * NP + NT + tid];

    // ---- final bitonic merge phase k=2048 ----
    {
        ull mx = e0 > e1 ? e0 : e1;
        ull mn = e0 > e1 ? e1 : e0;
        e0 = mx; e1 = mn;
    }
    int cur = 0;
    #pragma unroll
    for (int jj = 512; jj >= 32; jj >>= 1) {
        sm.kbuf[cur][tid]      = e0;
        sm.kbuf[cur][tid + NT] = e1;
        __syncthreads();
        ull p0 = sm.kbuf[cur][tid ^ jj];
        ull p1 = sm.kbuf[cur][(tid + NT) ^ jj];
        bool tm = (tid & jj) == 0;
        e0 = tm ? (e0 > p0 ? e0 : p0) : (e0 < p0 ? e0 : p0);
        e1 = tm ? (e1 > p1 ? e1 : p1) : (e1 < p1 ? e1 : p1);
        cur ^= 1;
    }
    #pragma unroll
    for (int jj = 16; jj >= 1; jj >>= 1) {
        ull p0 = __shfl_xor_sync(FULL, e0, jj);
        ull p1 = __shfl_xor_sync(FULL, e1, jj);
        bool tm = (lane & jj) == 0;
        e0 = tm ? (e0 > p0 ? e0 : p0) : (e0 < p0 ? e0 : p0);
        e1 = tm ? (e1 > p1 ? e1 : p1) : (e1 < p1 ? e1 : p1);
    }
    sm.kbuf[cur][tid]      = e0;
    sm.kbuf[cur][tid + NT] = e1;
    __syncthreads();
    const ull* kk = sm.kbuf[cur];
    const float4* boxes = g_box + (size_t)b * NP;

    // ---- windowed greedy NMS, 3 barriers/window ----
    int cnt = 0;
    for (int wp = 0; wp < NP; wp += WIN) {
        // AB2: all 1024 threads; candidate i = tid>>3, 8-way-split keep tests
        {
            int i   = tid >> 3;
            int sub = tid & 7;
            ull kye = kk[wp + i];
            unsigned ki = (unsigned)(kye >> 32);
            bool v = ki >= 0x80000000u;
            int orig = NP - 1 - (int)(unsigned)kye;
            float4 bi = boxes[orig];
            float  ar = (bi.z - bi.x) * (bi.w - bi.y);
            float  api = ar + 1e-9f;
            bool sup = false;
            if (v) {
                #pragma unroll 4
                for (int t = sub; t < cnt; t += 8) {
                    float4 kb = sm.kbox[t];
                    float  ka = sm.karea[t];
                    float iw = fmaxf(fminf(kb.z, bi.z) - fmaxf(kb.x, bi.x), 0.0f);
                    float ih = fmaxf(fminf(kb.w, bi.w) - fmaxf(kb.y, bi.y), 0.0f);
                    sup = sup || (3.5f * (iw * ih) > ka + api);   // iou > 0.4
                }
            }
            unsigned m = __ballot_sync(FULL, sup);
            if (sub == 0) {
                sm.wbox[i]  = bi;
                sm.warea[i] = ar;
                sm.wkey[i]  = ki;
                bool ok = v && (((m >> (lane & 24)) & 0xFFu) == 0u);
                sm.okarr[i] = ok ? 1 : 0;
            }
        }
        __syncthreads();

        // B1: kill masks for alive j (triangular zeros); warp 16 packs alive words
        if (tid < 512) {
            int j  = tid & 127;
            int wd = tid >> 7;
            if (sm.okarr[j]) {
                if (((wd << 5) | 31) <= j) {
                    sm.mask[j][wd] = 0u;
                } else {
                    float4 bj = sm.wbox[j];
                    float  aj = sm.warea[j];
                    unsigned m = 0u;
                    #pragma unroll 8
                    for (int i2 = 0; i2 < 32; ++i2) {
                        int i = (wd << 5) | i2;
                        float4 bi  = sm.wbox[i];
                        float  api = sm.warea[i] + 1e-9f;
                        float iw = fmaxf(fminf(bj.z, bi.z) - fmaxf(bj.x, bi.x), 0.0f);
                        float ih = fmaxf(fminf(bj.w, bi.w) - fmaxf(bj.y, bi.y), 0.0f);
                        bool kill = (3.5f * (iw * ih) > aj + api) && (i > j);
                        m |= kill ? (1u << i2) : 0u;
                    }
                    sm.mask[j][wd] = m;
                }
            }
        } else if (tid < 544) {
            int l = tid - 512;
            unsigned w0 = __ballot_sync(FULL, sm.okarr[l]      != 0);
            unsigned w1 = __ballot_sync(FULL, sm.okarr[32 + l] != 0);
            unsigned w2 = __ballot_sync(FULL, sm.okarr[64 + l] != 0);
            unsigned w3 = __ballot_sync(FULL, sm.okarr[96 + l] != 0);
            if (l == 0) { sm.alive[0] = w0; sm.alive[1] = w1; sm.alive[2] = w2; sm.alive[3] = w3; }
        }
        __syncthreads();

        // C: warp 0 — serial resolve (lane 0) + parallel keep copy
        if (tid < 32) {
            if (lane == 0) {
                unsigned a0 = sm.alive[0], a1 = sm.alive[1], a2 = sm.alive[2], a3 = sm.alive[3];
                int cc = cnt;
                while (a0 && cc < DETK) {
                    int i = __ffs(a0) - 1;
                    a0 &= a0 - 1;
                    uint4 m = *reinterpret_cast<const uint4*>(sm.mask[i]);
                    a0 &= ~m.x; a1 &= ~m.y; a2 &= ~m.z; a3 &= ~m.w;
                    sm.keepwin[cc++] = i;
                }
                while (a1 && cc < DETK) {
                    int i = 32 + (__ffs(a1) - 1);
                    a1 &= a1 - 1;
                    uint4 m = *reinterpret_cast<const uint4*>(sm.mask[i]);
                    a1 &= ~m.y; a2 &= ~m.z; a3 &= ~m.w;
                    sm.keepwin[cc++] = i;
                }
                while (a2 && cc < DETK) {
                    int i = 64 + (__ffs(a2) - 1);
                    a2 &= a2 - 1;
                    uint4 m = *reinterpret_cast<const uint4*>(sm.mask[i]);
                    a2 &= ~m.z; a3 &= ~m.w;
                    sm.keepwin[cc++] = i;
                }
                while (a3 && cc < DETK) {
                    int i = 96 + (__ffs(a3) - 1);
                    a3 &= a3 - 1;
                    uint4 m = *reinterpret_cast<const uint4*>(sm.mask[i]);
                    a3 &= ~m.w;
                    sm.keepwin[cc++] = i;
                }
                sm.cnt  = cc;
                sm.stop = (cc >= DETK || sm.wkey[WIN - 1] < 0x80000000u) ? 1 : 0;
            }
            __syncwarp();
            int newcnt = sm.cnt;
            for (int c2 = cnt + lane; c2 < newcnt; c2 += 32) {
                int i = sm.keepwin[c2];
                sm.kbox[c2]    = sm.wbox[i];
                sm.karea[c2]   = sm.warea[i];
                sm.keepkey[c2] = sm.wkey[i];
            }
        }
        __syncthreads();
        cnt = sm.cnt;
        if (sm.stop) break;
    }

    // ---- outputs [boxes 3200 | scores 800 | classes 800 | valid 800] ----
    if (tid < DETK) {
        int k = tid;
        float4 ob = make_float4(0.f, 0.f, 0.f, 0.f);
        float os = 0.f, oc = 0.f, ov = 0.f;
        if (k < cnt) {
            ob = sm.kbox[k];
            os = s2f(sm.keepkey[k]);
            oc = 1.0f;
            ov = 1.0f;
        }
        float* obp = out + ((size_t)b * DETK + k) * 4;
        obp[0] = ob.x; obp[1] = ob.y; obp[2] = ob.z; obp[3] = ob.w;
        const int SB = BN * DETK * 4;   // 3200
        const int SC = BN * DETK;       // 800
        out[SB +          b * DETK + k] = os;
        out[SB + SC +     b * DETK + k] = oc;
        out[SB + 2 * SC + b * DETK + k] = ov;
    }
}

extern "C" void kernel_launch(void* const* d_in, const int* in_sizes, int n_in,
                              void* d_out, int out_size) {
    const float* clss  = (const float*)d_in[0];
    const float* regs  = (const float*)d_in[1];
    const float* qlts  = (const float*)d_in[2];
    const float* props = (const float*)d_in[3];
    float* out = (float*)d_out;

    k1_decode_sort<<<BN * 2, NT>>>(clss, regs, qlts, props);
    k2_merge_nms<<<BN, NT>>>(out);
}

// round 14
// speedup vs baseline: 1.2309x; 1.2309x over previous
#include <cuda_runtime.h>

#define BN   8
#define NP   2048
#define DETK 100
#define NT   1024
#define WIN  128
#define FULL 0xffffffffu

typedef unsigned long long ull;

// Inter-kernel scratch (allocation-free: __device__ globals)
__device__ ull    g_keys[BN * NP];
__device__ float4 g_box [BN * NP];

static __device__ __forceinline__ float stable_sigmoid(float d) {
    return (d >= 0.0f) ? (1.0f / (1.0f + expf(-d)))
                       : (expf(d) / (1.0f + expf(d)));
}
static __device__ __forceinline__ unsigned f2s(float f) {
    unsigned u = __float_as_uint(f);
    return (u & 0x80000000u) ? ~u : (u | 0x80000000u);
}
static __device__ __forceinline__ float s2f(unsigned u) {
    u = (u & 0x80000000u) ? (u & 0x7FFFFFFFu) : ~u;
    return __uint_as_float(u);
}

// ---------------- Kernel 1: decode half-image + sort its 1024 keys ----------------
__global__ __launch_bounds__(NT, 1)
void k1_decode_sort(const float* __restrict__ clss,
                    const float* __restrict__ regs,
                    const float* __restrict__ qlts,
                    const float* __restrict__ props)
{
    __shared__ ull kb[2][NT];

    const int b    = blockIdx.x >> 1;
    const int h    = blockIdx.x & 1;
    const int tid  = threadIdx.x;
    const int lane = tid & 31;
    const int g    = (h << 10) | tid;

    const float W_IMG = 1344.0f, H_IMG = 800.0f;
    const float CLIPV = 4.135166556742356f;   // log(1000/16)

    const float2* cls = (const float2*)(clss  + (size_t)b * NP * 2);
    const float4* reg = (const float4*)(regs  + (size_t)b * NP * 4);
    const float*  qlt =                 qlts  + (size_t)b * NP;
    const float4* prp = (const float4*)(props + (size_t)b * NP * 4);

    float4 p = prp[g];
    float bw = p.z - p.x, bh = p.w - p.y;
    float cx = p.x + 0.5f * bw, cy = p.y + 0.5f * bh;

    float4 r = reg[g];
    float dx = r.x * 0.1f;
    float dy = r.y * 0.1f;
    float dw = fminf(r.z * 0.2f, CLIPV);
    float dh = fminf(r.w * 0.2f, CLIPV);

    float pcx = dx * bw + cx;
    float pcy = dy * bh + cy;
    float pw  = expf(dw) * bw;
    float ph  = expf(dh) * bh;

    float x1 = fminf(fmaxf(pcx - 0.5f * pw, 0.0f), W_IMG);
    float y1 = fminf(fmaxf(pcy - 0.5f * ph, 0.0f), H_IMG);
    float x2 = fminf(fmaxf(pcx + 0.5f * pw, 0.0f), W_IMG);
    float y2 = fminf(fmaxf(pcy + 0.5f * ph, 0.0f), H_IMG);

    bool small_keep = ((x2 - x1) >= 0.01f) && ((y2 - y1) >= 0.01f);

    float2 c = cls[g];
    float raw = stable_sigmoid(c.y - c.x);
    bool  score_keep = raw > 0.5f;
    float score = stable_sigmoid(qlt[g]) * raw;

    bool valid = small_keep && score_keep;
    unsigned k32 = valid ? f2s(score) : 0u;   // valid <=> k32 >= 0x80000000

    g_box[b * NP + g] = make_float4(x1, y1, x2, y2);
    ull key = ((ull)k32 << 32) | (unsigned)(NP - 1 - g);

    // half-sort: direction from GLOBAL index g (half0 desc, half1 asc)
    int cur = 0;
    #pragma unroll
    for (int k = 2; k <= 1024; k <<= 1) {
        #pragma unroll
        for (int jj = k >> 1; jj > 0; jj >>= 1) {
            if (jj >= 32) {
                kb[cur][tid] = key;
                __syncthreads();
                ull pk = kb[cur][tid ^ jj];
                bool tm = ((g & k) == 0) != ((tid & jj) != 0);
                key = tm ? (key > pk ? key : pk) : (key < pk ? key : pk);
                cur ^= 1;
            } else {
                ull pk = __shfl_xor_sync(FULL, key, jj);
                bool tm = ((g & k) == 0) != ((lane & jj) != 0);
                key = tm ? (key > pk ? key : pk) : (key < pk ? key : pk);
            }
        }
    }
    g_keys[b * NP + g] = key;

    // PDL: allow dependent kernel to begin launching (memory visibility is
    // enforced by griddepcontrol.wait in the dependent).
    asm volatile("griddepcontrol.launch_dependents;");
}

// ---------------- Kernel 2: merge + killer-skipping mask NMS + output ----------------
struct Smem2 {
    ull      kbuf[2][NP];            // merge exchange buffers (32 KB)
    float4   wbox[WIN];
    float    warea[WIN];
    unsigned wkey[WIN];
    alignas(16) unsigned mask[WIN][4];
    int      okarr[WIN];
    unsigned alive[4];
    unsigned killerpart[4][4];       // [wd][jword] ballot of (mask[j][wd] != 0)
    unsigned finalm[4];              // kept bitmask for this window
    float4   kbox[DETK];
    float    karea[DETK];
    unsigned keepkey[DETK];
    int      cnt;
    int      stop;
};

__global__ __launch_bounds__(NT, 1)
void k2_merge_nms(float* __restrict__ out)
{
    asm volatile("griddepcontrol.wait;");   // PDL: wait for k1's writes

    __shared__ Smem2 sm;

    const int b    = blockIdx.x;
    const int tid  = threadIdx.x;
    const int lane = tid & 31;

    ull e0 = g_keys[b * NP + tid];
    ull e1 = g_keys[b * NP + NT + tid];

    // ---- final bitonic merge phase k=2048 ----
    {
        ull mx = e0 > e1 ? e0 : e1;
        ull mn = e0 > e1 ? e1 : e0;
        e0 = mx; e1 = mn;
    }
    int cur = 0;
    #pragma unroll
    for (int jj = 512; jj >= 32; jj >>= 1) {
        sm.kbuf[cur][tid]      = e0;
        sm.kbuf[cur][tid + NT] = e1;
        __syncthreads();
        ull p0 = sm.kbuf[cur][tid ^ jj];
        ull p1 = sm.kbuf[cur][(tid + NT) ^ jj];
        bool tm = (tid & jj) == 0;
        e0 = tm ? (e0 > p0 ? e0 : p0) : (e0 < p0 ? e0 : p0);
        e1 = tm ? (e1 > p1 ? e1 : p1) : (e1 < p1 ? e1 : p1);
        cur ^= 1;
    }
    #pragma unroll
    for (int jj = 16; jj >= 1; jj >>= 1) {
        ull p0 = __shfl_xor_sync(FULL, e0, jj);
        ull p1 = __shfl_xor_sync(FULL, e1, jj);
        bool tm = (lane & jj) == 0;
        e0 = tm ? (e0 > p0 ? e0 : p0) : (e0 < p0 ? e0 : p0);
        e1 = tm ? (e1 > p1 ? e1 : p1) : (e1 < p1 ? e1 : p1);
    }
    sm.kbuf[cur][tid]      = e0;
    sm.kbuf[cur][tid + NT] = e1;
    __syncthreads();
    const ull* kk = sm.kbuf[cur];
    const float4* boxes = g_box + (size_t)b * NP;

    // ---- windowed greedy NMS, 3 barriers/window ----
    int cnt = 0;
    for (int wp = 0; wp < NP; wp += WIN) {
        // AB2: all 1024 threads; candidate i = tid>>3, 8-way-split keep tests
        {
            int i   = tid >> 3;
            int sub = tid & 7;
            ull kye = kk[wp + i];
            unsigned ki = (unsigned)(kye >> 32);
            bool v = ki >= 0x80000000u;
            int orig = NP - 1 - (int)(unsigned)kye;
            float4 bi = boxes[orig];
            float  ar = (bi.z - bi.x) * (bi.w - bi.y);
            float  api = ar + 1e-9f;
            bool sup = false;
            if (v) {
                #pragma unroll 4
                for (int t = sub; t < cnt; t += 8) {
                    float4 kb = sm.kbox[t];
                    float  ka = sm.karea[t];
                    float iw = fmaxf(fminf(kb.z, bi.z) - fmaxf(kb.x, bi.x), 0.0f);
                    float ih = fmaxf(fminf(kb.w, bi.w) - fmaxf(kb.y, bi.y), 0.0f);
                    sup = sup || (3.5f * (iw * ih) > ka + api);   // iou > 0.4
                }
            }
            unsigned m = __ballot_sync(FULL, sup);
            if (sub == 0) {
                sm.wbox[i]  = bi;
                sm.warea[i] = ar;
                sm.wkey[i]  = ki;
                bool ok = v && (((m >> (lane & 24)) & 0xFFu) == 0u);
                sm.okarr[i] = ok ? 1 : 0;
            }
        }
        __syncthreads();

        // B1: kill masks (always written; dead/triangular rows = 0) + killer ballots
        if (tid < 512) {
            int j  = tid & 127;          // warp w = tid>>5: wd = w>>2, jword = w&3
            int wd = tid >> 7;
            unsigned m = 0u;
            if (sm.okarr[j] && (((wd << 5) | 31) > j)) {
                float4 bj = sm.wbox[j];
                float  aj = sm.warea[j];
                #pragma unroll 8
                for (int i2 = 0; i2 < 32; ++i2) {
                    int i = (wd << 5) | i2;
                    float4 bi  = sm.wbox[i];
                    float  api = sm.warea[i] + 1e-9f;
                    float iw = fmaxf(fminf(bj.z, bi.z) - fmaxf(bj.x, bi.x), 0.0f);
                    float ih = fmaxf(fminf(bj.w, bi.w) - fmaxf(bj.y, bi.y), 0.0f);
                    bool kill = (3.5f * (iw * ih) > aj + api) && (i > j);
                    m |= kill ? (1u << i2) : 0u;
                }
            }
            sm.mask[j][wd] = m;
            unsigned kp = __ballot_sync(FULL, m != 0u);
            if (lane == 0) sm.killerpart[tid >> 7][(tid >> 5) & 3] = kp;
        } else if (tid < 544) {
            int l = tid - 512;
            unsigned w0 = __ballot_sync(FULL, sm.okarr[l]      != 0);
            unsigned w1 = __ballot_sync(FULL, sm.okarr[32 + l] != 0);
            unsigned w2 = __ballot_sync(FULL, sm.okarr[64 + l] != 0);
            unsigned w3 = __ballot_sync(FULL, sm.okarr[96 + l] != 0);
            if (l == 0) { sm.alive[0] = w0; sm.alive[1] = w1; sm.alive[2] = w2; sm.alive[3] = w3; }
        }
        __syncthreads();

        // R+E: warp 0 — killer-skipping resolve (lane 0) + parallel rank emission
        if (tid < 32) {
            if (lane == 0) {
                unsigned killer[4], a[4], fin[4];
                #pragma unroll
                for (int c2 = 0; c2 < 4; ++c2) {
                    killer[c2] = sm.killerpart[0][c2] | sm.killerpart[1][c2]
                               | sm.killerpart[2][c2] | sm.killerpart[3][c2];
                    a[c2]   = sm.alive[c2];
                    fin[c2] = 0u;
                }
                #pragma unroll
                for (int wd2 = 0; wd2 < 4; ++wd2) {
                    unsigned aa = a[wd2];
                    unsigned kw = aa & killer[wd2];
                    while (kw) {
                        int ik = __ffs(kw) - 1;
                        unsigned lowm = (1u << ik) - 1u;
                        fin[wd2] |= (aa & lowm) | (1u << ik);   // keep non-killers below + killer
                        uint4 mm = *reinterpret_cast<const uint4*>(sm.mask[(wd2 << 5) | ik]);
                        aa &= ~(lowm | (1u << ik));
                        const unsigned mw[4] = { mm.x, mm.y, mm.z, mm.w };
                        aa &= ~mw[wd2];
                        #pragma unroll
                        for (int w3 = 0; w3 < 4; ++w3)
                            if (w3 > wd2) a[w3] &= ~mw[w3];
                        kw = aa & killer[wd2];
                    }
                    fin[wd2] |= aa;     // remaining alive are all non-killers -> kept
                }
                int tot = __popc(fin[0]) + __popc(fin[1]) + __popc(fin[2]) + __popc(fin[3]);
                int lim = DETK - cnt;
                sm.finalm[0] = fin[0]; sm.finalm[1] = fin[1];
                sm.finalm[2] = fin[2]; sm.finalm[3] = fin[3];
                int newcnt = cnt + (tot < lim ? tot : lim);
                sm.cnt  = newcnt;
                sm.stop = (newcnt >= DETK || sm.wkey[WIN - 1] < 0x80000000u) ? 1 : 0;
            }
            __syncwarp();
            unsigned f0 = sm.finalm[0], f1 = sm.finalm[1], f2 = sm.finalm[2], f3 = sm.finalm[3];
            int base1 = __popc(f0);
            int base2 = base1 + __popc(f1);
            int base3 = base2 + __popc(f2);
            int lim = DETK - cnt;
            unsigned lb = (1u << lane) - 1u;
            #pragma unroll
            for (int c2 = 0; c2 < 4; ++c2) {
                unsigned f = (c2 == 0) ? f0 : (c2 == 1) ? f1 : (c2 == 2) ? f2 : f3;
                int base  = (c2 == 0) ? 0  : (c2 == 1) ? base1 : (c2 == 2) ? base2 : base3;
                if ((f >> lane) & 1u) {
                    int rank = base + __popc(f & lb);
                    if (rank < lim) {
                        int i   = (c2 << 5) | lane;
                        int idx = cnt + rank;
                        sm.kbox[idx]    = sm.wbox[i];
                        sm.karea[idx]   = sm.warea[i];
                        sm.keepkey[idx] = sm.wkey[i];
                    }
                }
            }
        }
        __syncthreads();
        cnt = sm.cnt;
        if (sm.stop) break;
    }

    // ---- outputs [boxes 3200 | scores 800 | classes 800 | valid 800] ----
    if (tid < DETK) {
        int k = tid;
        float4 ob = make_float4(0.f, 0.f, 0.f, 0.f);
        float os = 0.f, oc = 0.f, ov = 0.f;
        if (k < cnt) {
            ob = sm.kbox[k];
            os = s2f(sm.keepkey[k]);
            oc = 1.0f;
            ov = 1.0f;
        }
        float* obp = out + ((size_t)b * DETK + k) * 4;
        obp[0] = ob.x; obp[1] = ob.y; obp[2] = ob.z; obp[3] = ob.w;
        const int SB = BN * DETK * 4;   // 3200
        const int SC = BN * DETK;       // 800
        out[SB +          b * DETK + k] = os;
        out[SB + SC +     b * DETK + k] = oc;
        out[SB + 2 * SC + b * DETK + k] = ov;
    }
}

extern "C" void kernel_launch(void* const* d_in, const int* in_sizes, int n_in,
                              void* d_out, int out_size) {
    const float* clss  = (const float*)d_in[0];
    const float* regs  = (const float*)d_in[1];
    const float* qlts  = (const float*)d_in[2];
    const float* props = (const float*)d_in[3];
    float* out = (float*)d_out;

    k1_decode_sort<<<BN * 2, NT>>>(clss, regs, qlts, props);

    // k2 with Programmatic Dependent Launch: overlap its launch with k1's tail.
    cudaLaunchConfig_t cfg = {};
    cfg.gridDim  = dim3(BN, 1, 1);
    cfg.blockDim = dim3(NT, 1, 1);
    cudaLaunchAttribute attrs[1];
    attrs[0].id = cudaLaunchAttributeProgrammaticStreamSerialization;
    attrs[0].val.programmaticStreamSerializationAllowed = 1;
    cfg.attrs    = attrs;
    cfg.numAttrs = 1;
    cudaLaunchKernelEx(&cfg, k2_merge_nms, (float*)d_out);
}

// round 15
// speedup vs baseline: 1.3794x; 1.1206x over previous
#include <cuda_runtime.h>

#define BN   8
#define NP   2048
#define DETK 100
#define NT   1024
#define WIN  128
#define FULL 0xffffffffu

typedef unsigned long long ull;

// Inter-kernel scratch (allocation-free: __device__ globals)
__device__ ull    g_keys[BN * NP];
__device__ float4 g_box [BN * NP];

static __device__ __forceinline__ float stable_sigmoid(float d) {
    return (d >= 0.0f) ? (1.0f / (1.0f + expf(-d)))
                       : (expf(d) / (1.0f + expf(d)));
}
static __device__ __forceinline__ unsigned f2s(float f) {
    unsigned u = __float_as_uint(f);
    return (u & 0x80000000u) ? ~u : (u | 0x80000000u);
}
static __device__ __forceinline__ float s2f(unsigned u) {
    u = (u & 0x80000000u) ? (u & 0x7FFFFFFFu) : ~u;
    return __uint_as_float(u);
}

// ---------------- Kernel 1: decode half-image + sort its 1024 keys (unchanged R14) ----------------
__global__ __launch_bounds__(NT, 1)
void k1_decode_sort(const float* __restrict__ clss,
                    const float* __restrict__ regs,
                    const float* __restrict__ qlts,
                    const float* __restrict__ props)
{
    __shared__ ull kb[2][NT];

    const int b    = blockIdx.x >> 1;
    const int h    = blockIdx.x & 1;
    const int tid  = threadIdx.x;
    const int lane = tid & 31;
    const int g    = (h << 10) | tid;

    const float W_IMG = 1344.0f, H_IMG = 800.0f;
    const float CLIPV = 4.135166556742356f;   // log(1000/16)

    const float2* cls = (const float2*)(clss  + (size_t)b * NP * 2);
    const float4* reg = (const float4*)(regs  + (size_t)b * NP * 4);
    const float*  qlt =                 qlts  + (size_t)b * NP;
    const float4* prp = (const float4*)(props + (size_t)b * NP * 4);

    float4 p = prp[g];
    float bw = p.z - p.x, bh = p.w - p.y;
    float cx = p.x + 0.5f * bw, cy = p.y + 0.5f * bh;

    float4 r = reg[g];
    float dx = r.x * 0.1f;
    float dy = r.y * 0.1f;
    float dw = fminf(r.z * 0.2f, CLIPV);
    float dh = fminf(r.w * 0.2f, CLIPV);

    float pcx = dx * bw + cx;
    float pcy = dy * bh + cy;
    float pw  = expf(dw) * bw;
    float ph  = expf(dh) * bh;

    float x1 = fminf(fmaxf(pcx - 0.5f * pw, 0.0f), W_IMG);
    float y1 = fminf(fmaxf(pcy - 0.5f * ph, 0.0f), H_IMG);
    float x2 = fminf(fmaxf(pcx + 0.5f * pw, 0.0f), W_IMG);
    float y2 = fminf(fmaxf(pcy + 0.5f * ph, 0.0f), H_IMG);

    bool small_keep = ((x2 - x1) >= 0.01f) && ((y2 - y1) >= 0.01f);

    float2 c = cls[g];
    float raw = stable_sigmoid(c.y - c.x);
    bool  score_keep = raw > 0.5f;
    float score = stable_sigmoid(qlt[g]) * raw;

    bool valid = small_keep && score_keep;
    unsigned k32 = valid ? f2s(score) : 0u;   // valid <=> k32 >= 0x80000000

    g_box[b * NP + g] = make_float4(x1, y1, x2, y2);
    ull key = ((ull)k32 << 32) | (unsigned)(NP - 1 - g);

    // half-sort: direction from GLOBAL index g (half0 desc, half1 asc)
    int cur = 0;
    #pragma unroll
    for (int k = 2; k <= 1024; k <<= 1) {
        #pragma unroll
        for (int jj = k >> 1; jj > 0; jj >>= 1) {
            if (jj >= 32) {
                kb[cur][tid] = key;
                __syncthreads();
                ull pk = kb[cur][tid ^ jj];
                bool tm = ((g & k) == 0) != ((tid & jj) != 0);
                key = tm ? (key > pk ? key : pk) : (key < pk ? key : pk);
                cur ^= 1;
            } else {
                ull pk = __shfl_xor_sync(FULL, key, jj);
                bool tm = ((g & k) == 0) != ((lane & jj) != 0);
                key = tm ? (key > pk ? key : pk) : (key < pk ? key : pk);
            }
        }
    }
    g_keys[b * NP + g] = key;

    asm volatile("griddepcontrol.launch_dependents;");
}

// ---------------- Kernel 2: merge-path windowed NMS + output ----------------
struct Smem2 {
    ull      sA[1024];               // half0, descending (8 KB)
    ull      sB[1024];               // half1 reversed -> descending (8 KB)
    float4   wbox[WIN];
    float    warea[WIN];
    unsigned wkey[WIN];
    alignas(16) unsigned mask[WIN][4];
    int      okarr[WIN];
    unsigned alive[4];
    unsigned killerpart[4][4];
    unsigned finalm[4];
    float4   kbox[DETK];
    float    karea[DETK];
    unsigned keepkey[DETK];
    int      cnt;
    int      stop;
};

__global__ __launch_bounds__(NT, 1)
void k2_merge_nms(float* __restrict__ out)
{
    asm volatile("griddepcontrol.wait;");   // PDL: wait for k1's writes

    __shared__ Smem2 sm;

    const int b    = blockIdx.x;
    const int tid  = threadIdx.x;
    const int lane = tid & 31;

    const ull*    gk    = g_keys + (size_t)b * NP;
    const float4* boxes = g_box  + (size_t)b * NP;

    // Load both sorted halves into smem (half1 reversed to descending).
    sm.sA[tid] = gk[tid];
    sm.sB[tid] = gk[2047 - tid];
    __syncthreads();

    // ---- windowed greedy NMS, merge-path candidate extraction ----
    int cnt = 0;
    for (int wp = 0; wp < NP; wp += WIN) {
        // M: threads 0..127 compute merged rank wp+t via merge-path binary search
        if (tid < WIN) {
            int r  = wp + tid;
            int lo = r > 1024 ? r - 1024 : 0;
            int hi = r < 1024 ? r : 1024;
            while (lo < hi) {
                int mid = (lo + hi) >> 1;
                if (sm.sA[mid] > sm.sB[r - 1 - mid]) lo = mid + 1; else hi = mid;
            }
            int j = r - lo;
            ull aH = (lo < 1024) ? sm.sA[lo] : 0ull;
            ull bH = (j  < 1024) ? sm.sB[j]  : 0ull;
            ull key = aH > bH ? aH : bH;

            unsigned k32 = (unsigned)(key >> 32);
            int orig = NP - 1 - (int)(unsigned)key;
            float4 bx = boxes[orig];
            sm.wkey[tid]  = k32;
            sm.wbox[tid]  = bx;
            sm.warea[tid] = (bx.z - bx.x) * (bx.w - bx.y);
        }
        __syncthreads();

        // AB2: all 1024 threads; candidate i = tid>>3, 8-way-split keep tests
        {
            int i   = tid >> 3;
            int sub = tid & 7;
            unsigned ki = sm.wkey[i];
            bool v = ki >= 0x80000000u;
            float4 bi = sm.wbox[i];
            float  api = sm.warea[i] + 1e-9f;
            bool sup = false;
            if (v) {
                #pragma unroll 4
                for (int t = sub; t < cnt; t += 8) {
                    float4 kb = sm.kbox[t];
                    float  ka = sm.karea[t];
                    float iw = fmaxf(fminf(kb.z, bi.z) - fmaxf(kb.x, bi.x), 0.0f);
                    float ih = fmaxf(fminf(kb.w, bi.w) - fmaxf(kb.y, bi.y), 0.0f);
                    sup = sup || (3.5f * (iw * ih) > ka + api);   // iou > 0.4
                }
            }
            unsigned m = __ballot_sync(FULL, sup);
            if (sub == 0) {
                bool ok = v && (((m >> (lane & 24)) & 0xFFu) == 0u);
                sm.okarr[i] = ok ? 1 : 0;
            }
        }
        __syncthreads();

        // B1: kill masks (dead/triangular rows = 0) + killer ballots
        if (tid < 512) {
            int j  = tid & 127;
            int wd = tid >> 7;
            unsigned m = 0u;
            if (sm.okarr[j] && (((wd << 5) | 31) > j)) {
                float4 bj = sm.wbox[j];
                float  aj = sm.warea[j];
                #pragma unroll 8
                for (int i2 = 0; i2 < 32; ++i2) {
                    int i = (wd << 5) | i2;
                    float4 bi  = sm.wbox[i];
                    float  api = sm.warea[i] + 1e-9f;
                    float iw = fmaxf(fminf(bj.z, bi.z) - fmaxf(bj.x, bi.x), 0.0f);
                    float ih = fmaxf(fminf(bj.w, bi.w) - fmaxf(bj.y, bi.y), 0.0f);
                    bool kill = (3.5f * (iw * ih) > aj + api) && (i > j);
                    m |= kill ? (1u << i2) : 0u;
                }
            }
            sm.mask[j][wd] = m;
            unsigned kp = __ballot_sync(FULL, m != 0u);
            if (lane == 0) sm.killerpart[tid >> 7][(tid >> 5) & 3] = kp;
        } else if (tid < 544) {
            int l = tid - 512;
            unsigned w0 = __ballot_sync(FULL, sm.okarr[l]      != 0);
            unsigned w1 = __ballot_sync(FULL, sm.okarr[32 + l] != 0);
            unsigned w2 = __ballot_sync(FULL, sm.okarr[64 + l] != 0);
            unsigned w3 = __ballot_sync(FULL, sm.okarr[96 + l] != 0);
            if (l == 0) { sm.alive[0] = w0; sm.alive[1] = w1; sm.alive[2] = w2; sm.alive[3] = w3; }
        }
        __syncthreads();

        // R+E: warp 0 — killer-skipping resolve (lane 0) + parallel rank emission
        if (tid < 32) {
            if (lane == 0) {
                unsigned killer[4], a[4], fin[4];
                #pragma unroll
                for (int c2 = 0; c2 < 4; ++c2) {
                    killer[c2] = sm.killerpart[0][c2] | sm.killerpart[1][c2]
                               | sm.killerpart[2][c2] | sm.killerpart[3][c2];
                    a[c2]   = sm.alive[c2];
                    fin[c2] = 0u;
                }
                #pragma unroll
                for (int wd2 = 0; wd2 < 4; ++wd2) {
                    unsigned aa = a[wd2];
                    unsigned kw = aa & killer[wd2];
                    while (kw) {
                        int ik = __ffs(kw) - 1;
                        unsigned lowm = (1u << ik) - 1u;
                        fin[wd2] |= (aa & lowm) | (1u << ik);
                        uint4 mm = *reinterpret_cast<const uint4*>(sm.mask[(wd2 << 5) | ik]);
                        aa &= ~(lowm | (1u << ik));
                        const unsigned mw[4] = { mm.x, mm.y, mm.z, mm.w };
                        aa &= ~mw[wd2];
                        #pragma unroll
                        for (int w3 = 0; w3 < 4; ++w3)
                            if (w3 > wd2) a[w3] &= ~mw[w3];
                        kw = aa & killer[wd2];
                    }
                    fin[wd2] |= aa;
                }
                int tot = __popc(fin[0]) + __popc(fin[1]) + __popc(fin[2]) + __popc(fin[3]);
                int lim = DETK - cnt;
                sm.finalm[0] = fin[0]; sm.finalm[1] = fin[1];
                sm.finalm[2] = fin[2]; sm.finalm[3] = fin[3];
                int newcnt = cnt + (tot < lim ? tot : lim);
                sm.cnt  = newcnt;
                sm.stop = (newcnt >= DETK || sm.wkey[WIN - 1] < 0x80000000u) ? 1 : 0;
            }
            __syncwarp();
            unsigned f0 = sm.finalm[0], f1 = sm.finalm[1], f2 = sm.finalm[2], f3 = sm.finalm[3];
            int base1 = __popc(f0);
            int base2 = base1 + __popc(f1);
            int base3 = base2 + __popc(f2);
            int lim = DETK - cnt;
            unsigned lb = (1u << lane) - 1u;
            #pragma unroll
            for (int c2 = 0; c2 < 4; ++c2) {
                unsigned f = (c2 == 0) ? f0 : (c2 == 1) ? f1 : (c2 == 2) ? f2 : f3;
                int base  = (c2 == 0) ? 0  : (c2 == 1) ? base1 : (c2 == 2) ? base2 : base3;
                if ((f >> lane) & 1u) {
                    int rank = base + __popc(f & lb);
                    if (rank < lim) {
                        int i   = (c2 << 5) | lane;
                        int idx = cnt + rank;
                        sm.kbox[idx]    = sm.wbox[i];
                        sm.karea[idx]   = sm.warea[i];
                        sm.keepkey[idx] = sm.wkey[i];
                    }
                }
            }
        }
        __syncthreads();
        cnt = sm.cnt;
        if (sm.stop) break;
    }

    // ---- outputs [boxes 3200 | scores 800 | classes 800 | valid 800] ----
    if (tid < DETK) {
        int k = tid;
        float4 ob = make_float4(0.f, 0.f, 0.f, 0.f);
        float os = 0.f, oc = 0.f, ov = 0.f;
        if (k < cnt) {
            ob = sm.kbox[k];
            os = s2f(sm.keepkey[k]);
            oc = 1.0f;
            ov = 1.0f;
        }
        float* obp = out + ((size_t)b * DETK + k) * 4;
        obp[0] = ob.x; obp[1] = ob.y; obp[2] = ob.z; obp[3] = ob.w;
        const int SB = BN * DETK * 4;   // 3200
        const int SC = BN * DETK;       // 800
        out[SB +          b * DETK + k] = os;
        out[SB + SC +     b * DETK + k] = oc;
        out[SB + 2 * SC + b * DETK + k] = ov;
    }
}

extern "C" void kernel_launch(void* const* d_in, const int* in_sizes, int n_in,
                              void* d_out, int out_size) {
    const float* clss  = (const float*)d_in[0];
    const float* regs  = (const float*)d_in[1];
    const float* qlts  = (const float*)d_in[2];
    const float* props = (const float*)d_in[3];
    float* out = (float*)d_out;

    k1_decode_sort<<<BN * 2, NT>>>(clss, regs, qlts, props);

    cudaLaunchConfig_t cfg = {};
    cfg.gridDim  = dim3(BN, 1, 1);
    cfg.blockDim = dim3(NT, 1, 1);
    cudaLaunchAttribute attrs[1];
    attrs[0].id = cudaLaunchAttributeProgrammaticStreamSerialization;
    attrs[0].val.programmaticStreamSerializationAllowed = 1;
    cfg.attrs    = attrs;
    cfg.numAttrs = 1;
    cudaLaunchKernelEx(&cfg, k2_merge_nms, (float*)d_out);
}

// round 17
// speedup vs baseline: 1.5346x; 1.1126x over previous
#include <cuda_runtime.h>

#define BN   8
#define NP   2048
#define DETK 100
#define NT   1024
#define NQ   512
#define WIN  128
#define FULL 0xffffffffu

typedef unsigned long long ull;

// Inter-kernel scratch (allocation-free: __device__ globals)
__device__ ull    g_keys[BN * NP];
__device__ float4 g_box [BN * NP];

static __device__ __forceinline__ float stable_sigmoid(float d) {
    return (d >= 0.0f) ? (1.0f / (1.0f + expf(-d)))
                       : (expf(d) / (1.0f + expf(d)));
}
static __device__ __forceinline__ unsigned f2s(float f) {
    unsigned u = __float_as_uint(f);
    return (u & 0x80000000u) ? ~u : (u | 0x80000000u);
}
static __device__ __forceinline__ float s2f(unsigned u) {
    u = (u & 0x80000000u) ? (u & 0x7FFFFFFFu) : ~u;
    return __uint_as_float(u);
}

// -------- Kernel 1: decode quarter-image + sort its 512 keys DESCENDING --------
__global__ __launch_bounds__(NQ, 1)
void k1_decode_sort(const float* __restrict__ clss,
                    const float* __restrict__ regs,
                    const float* __restrict__ qlts,
                    const float* __restrict__ props)
{
    __shared__ ull kb[2][NQ];

    const int b    = blockIdx.x >> 2;
    const int q    = blockIdx.x & 3;
    const int tid  = threadIdx.x;          // 0..511
    const int lane = tid & 31;
    const int g    = (q << 9) | tid;       // global proposal index within image

    const float W_IMG = 1344.0f, H_IMG = 800.0f;
    const float CLIPV = 4.135166556742356f;   // log(1000/16)

    const float2* cls = (const float2*)(clss  + (size_t)b * NP * 2);
    const float4* reg = (const float4*)(regs  + (size_t)b * NP * 4);
    const float*  qlt =                 qlts  + (size_t)b * NP;
    const float4* prp = (const float4*)(props + (size_t)b * NP * 4);

    // ---- decode, clip, score (bit-identical math) ----
    float4 p = prp[g];
    float bw = p.z - p.x, bh = p.w - p.y;
    float cx = p.x + 0.5f * bw, cy = p.y + 0.5f * bh;

    float4 r = reg[g];
    float dx = r.x * 0.1f;
    float dy = r.y * 0.1f;
    float dw = fminf(r.z * 0.2f, CLIPV);
    float dh = fminf(r.w * 0.2f, CLIPV);

    float pcx = dx * bw + cx;
    float pcy = dy * bh + cy;
    float pw  = expf(dw) * bw;
    float ph  = expf(dh) * bh;

    float x1 = fminf(fmaxf(pcx - 0.5f * pw, 0.0f), W_IMG);
    float y1 = fminf(fmaxf(pcy - 0.5f * ph, 0.0f), H_IMG);
    float x2 = fminf(fmaxf(pcx + 0.5f * pw, 0.0f), W_IMG);
    float y2 = fminf(fmaxf(pcy + 0.5f * ph, 0.0f), H_IMG);

    bool small_keep = ((x2 - x1) >= 0.01f) && ((y2 - y1) >= 0.01f);

    float2 c = cls[g];
    float raw = stable_sigmoid(c.y - c.x);
    bool  score_keep = raw > 0.5f;
    float score = stable_sigmoid(qlt[g]) * raw;

    bool valid = small_keep && score_keep;
    unsigned k32 = valid ? f2s(score) : 0u;   // valid <=> k32 >= 0x80000000

    g_box[b * NP + g] = make_float4(x1, y1, x2, y2);
    ull key = ((ull)k32 << 32) | (unsigned)(NP - 1 - g);

    // ---- bitonic sort of 512 keys, descending (local-tid directions) ----
    int cur = 0;
    #pragma unroll
    for (int k = 2; k <= NQ; k <<= 1) {
        #pragma unroll
        for (int jj = k >> 1; jj > 0; jj >>= 1) {
            if (jj >= 32) {
                kb[cur][tid] = key;
                __syncthreads();
                ull pk = kb[cur][tid ^ jj];
                bool tm = ((tid & k) == 0) != ((tid & jj) != 0);
                key = tm ? (key > pk ? key : pk) : (key < pk ? key : pk);
                cur ^= 1;
            } else {
                ull pk = __shfl_xor_sync(FULL, key, jj);
                bool tm = ((tid & k) == 0) != ((lane & jj) != 0);
                key = tm ? (key > pk ? key : pk) : (key < pk ? key : pk);
            }
        }
    }
    g_keys[b * NP + g] = key;

    asm volatile("griddepcontrol.launch_dependents;");
}

// -------- Kernel 2: quarter-merge + merge-path windowed NMS + output --------
struct Smem2 {
    ull      qin[2048];              // 4 sorted quarters (16 KB)
    ull      sA[1024];               // merge(q0,q1), descending (8 KB)
    ull      sB[1024];               // merge(q2,q3), descending (8 KB)
    float4   wbox[WIN];
    float    warea[WIN];
    unsigned wkey[WIN];
    alignas(16) unsigned mask[WIN][4];
    int      okarr[WIN];
    unsigned alive[4];
    unsigned killerpart[4][4];
    unsigned finalm[4];
    float4   kbox[DETK];
    float    karea[DETK];
    unsigned keepkey[DETK];
    int      cnt;
    int      stop;
};

__global__ __launch_bounds__(NT, 1)
void k2_merge_nms(float* __restrict__ out)
{
    asm volatile("griddepcontrol.wait;");   // PDL: wait for k1's writes

    __shared__ Smem2 sm;

    const int b    = blockIdx.x;
    const int tid  = threadIdx.x;
    const int lane = tid & 31;

    const ull*    gk    = g_keys + (size_t)b * NP;
    const float4* boxes = g_box  + (size_t)b * NP;

    sm.qin[tid]        = gk[tid];
    sm.qin[tid + 1024] = gk[tid + 1024];
    __syncthreads();

    // ---- level-1 merge-path: quarters (0,1) -> sA, (2,3) -> sB, both descending ----
    {
        int r = tid;
        // merge(qin[0..511], qin[512..1023]) rank r
        {
            int lo = r > NQ ? r - NQ : 0;
            int hi = r < NQ ? r : NQ;
            while (lo < hi) {
                int mid = (lo + hi) >> 1;
                if (sm.qin[mid] > sm.qin[NQ + r - 1 - mid]) lo = mid + 1; else hi = mid;
            }
            int j = r - lo;
            ull aH = (lo < NQ) ? sm.qin[lo]      : 0ull;
            ull bH = (j  < NQ) ? sm.qin[NQ + j]  : 0ull;
            sm.sA[r] = aH > bH ? aH : bH;
        }
        // merge(qin[1024..1535], qin[1536..2047]) rank r
        {
            int lo = r > NQ ? r - NQ : 0;
            int hi = r < NQ ? r : NQ;
            while (lo < hi) {
                int mid = (lo + hi) >> 1;
                if (sm.qin[1024 + mid] > sm.qin[1536 + r - 1 - mid]) lo = mid + 1; else hi = mid;
            }
            int j = r - lo;
            ull aH = (lo < NQ) ? sm.qin[1024 + lo] : 0ull;
            ull bH = (j  < NQ) ? sm.qin[1536 + j]  : 0ull;
            sm.sB[r] = aH > bH ? aH : bH;
        }
    }
    __syncthreads();

    // ---- windowed greedy NMS, merge-path candidate extraction ----
    int cnt = 0;
    for (int wp = 0; wp < NP; wp += WIN) {
        // M: threads 0..127 compute merged rank wp+t via merge-path binary search
        if (tid < WIN) {
            int r  = wp + tid;
            int lo = r > 1024 ? r - 1024 : 0;
            int hi = r < 1024 ? r : 1024;
            while (lo < hi) {
                int mid = (lo + hi) >> 1;
                if (sm.sA[mid] > sm.sB[r - 1 - mid]) lo = mid + 1; else hi = mid;
            }
            int j = r - lo;
            ull aH = (lo < 1024) ? sm.sA[lo] : 0ull;
            ull bH = (j  < 1024) ? sm.sB[j]  : 0ull;
            ull key = aH > bH ? aH : bH;

            unsigned k32 = (unsigned)(key >> 32);
            int orig = NP - 1 - (int)(unsigned)key;
            float4 bx = boxes[orig];
            sm.wkey[tid]  = k32;
            sm.wbox[tid]  = bx;
            sm.warea[tid] = (bx.z - bx.x) * (bx.w - bx.y);
        }
        __syncthreads();

        // AB2: all 1024 threads; candidate i = tid>>3, 8-way-split keep tests
        {
            int i   = tid >> 3;
            int sub = tid & 7;
            unsigned ki = sm.wkey[i];
            bool v = ki >= 0x80000000u;
            float4 bi = sm.wbox[i];
            float  api = sm.warea[i] + 1e-9f;
            bool sup = false;
            if (v) {
                #pragma unroll 4
                for (int t = sub; t < cnt; t += 8) {
                    float4 kb = sm.kbox[t];
                    float  ka = sm.karea[t];
                    float iw = fmaxf(fminf(kb.z, bi.z) - fmaxf(kb.x, bi.x), 0.0f);
                    float ih = fmaxf(fminf(kb.w, bi.w) - fmaxf(kb.y, bi.y), 0.0f);
                    sup = sup || (3.5f * (iw * ih) > ka + api);   // iou > 0.4
                }
            }
            unsigned m = __ballot_sync(FULL, sup);
            if (sub == 0) {
                bool ok = v && (((m >> (lane & 24)) & 0xFFu) == 0u);
                sm.okarr[i] = ok ? 1 : 0;
            }
        }
        __syncthreads();

        // B1: kill masks (dead/triangular rows = 0) + killer ballots
        if (tid < 512) {
            int j  = tid & 127;
            int wd = tid >> 7;
            unsigned m = 0u;
            if (sm.okarr[j] && (((wd << 5) | 31) > j)) {
                float4 bj = sm.wbox[j];
                float  aj = sm.warea[j];
                #pragma unroll 8
                for (int i2 = 0; i2 < 32; ++i2) {
                    int i = (wd << 5) | i2;
                    float4 bi  = sm.wbox[i];
                    float  api = sm.warea[i] + 1e-9f;
                    float iw = fmaxf(fminf(bj.z, bi.z) - fmaxf(bj.x, bi.x), 0.0f);
                    float ih = fmaxf(fminf(bj.w, bi.w) - fmaxf(bj.y, bi.y), 0.0f);
                    bool kill = (3.5f * (iw * ih) > aj + api) && (i > j);
                    m |= kill ? (1u << i2) : 0u;
                }
            }
            sm.mask[j][wd] = m;
            unsigned kp = __ballot_sync(FULL, m != 0u);
            if (lane == 0) sm.killerpart[tid >> 7][(tid >> 5) & 3] = kp;
        } else if (tid < 544) {
            int l = tid - 512;
            unsigned w0 = __ballot_sync(FULL, sm.okarr[l]      != 0);
            unsigned w1 = __ballot_sync(FULL, sm.okarr[32 + l] != 0);
            unsigned w2 = __ballot_sync(FULL, sm.okarr[64 + l] != 0);
            unsigned w3 = __ballot_sync(FULL, sm.okarr[96 + l] != 0);
            if (l == 0) { sm.alive[0] = w0; sm.alive[1] = w1; sm.alive[2] = w2; sm.alive[3] = w3; }
        }
        __syncthreads();

        // R+E: warp 0 — killer-skipping resolve (lane 0) + parallel rank emission
        if (tid < 32) {
            if (lane == 0) {
                unsigned killer[4], a[4], fin[4];
                #pragma unroll
                for (int c2 = 0; c2 < 4; ++c2) {
                    killer[c2] = sm.killerpart[0][c2] | sm.killerpart[1][c2]
                               | sm.killerpart[2][c2] | sm.killerpart[3][c2];
                    a[c2]   = sm.alive[c2];
                    fin[c2] = 0u;
                }
                #pragma unroll
                for (int wd2 = 0; wd2 < 4; ++wd2) {
                    unsigned aa = a[wd2];
                    unsigned kw = aa & killer[wd2];
                    while (kw) {
                        int ik = __ffs(kw) - 1;
                        unsigned lowm = (1u << ik) - 1u;
                        fin[wd2] |= (aa & lowm) | (1u << ik);
                        uint4 mm = *reinterpret_cast<const uint4*>(sm.mask[(wd2 << 5) | ik]);
                        aa &= ~(lowm | (1u << ik));
                        const unsigned mw[4] = { mm.x, mm.y, mm.z, mm.w };
                        aa &= ~mw[wd2];
                        #pragma unroll
                        for (int w3 = 0; w3 < 4; ++w3)
                            if (w3 > wd2) a[w3] &= ~mw[w3];
                        kw = aa & killer[wd2];
                    }
                    fin[wd2] |= aa;
                }
                int tot = __popc(fin[0]) + __popc(fin[1]) + __popc(fin[2]) + __popc(fin[3]);
                int lim = DETK - cnt;
                sm.finalm[0] = fin[0]; sm.finalm[1] = fin[1];
                sm.finalm[2] = fin[2]; sm.finalm[3] = fin[3];
                int newcnt = cnt + (tot < lim ? tot : lim);
                sm.cnt  = newcnt;
                sm.stop = (newcnt >= DETK || sm.wkey[WIN - 1] < 0x80000000u) ? 1 : 0;
            }
            __syncwarp();
            unsigned f0 = sm.finalm[0], f1 = sm.finalm[1], f2 = sm.finalm[2], f3 = sm.finalm[3];
            int base1 = __popc(f0);
            int base2 = base1 + __popc(f1);
            int base3 = base2 + __popc(f2);
            int lim = DETK - cnt;
            unsigned lb = (1u << lane) - 1u;
            #pragma unroll
            for (int c2 = 0; c2 < 4; ++c2) {
                unsigned f = (c2 == 0) ? f0 : (c2 == 1) ? f1 : (c2 == 2) ? f2 : f3;
                int base  = (c2 == 0) ? 0  : (c2 == 1) ? base1 : (c2 == 2) ? base2 : base3;
                if ((f >> lane) & 1u) {
                    int rank = base + __popc(f & lb);
                    if (rank < lim) {
                        int i   = (c2 << 5) | lane;
                        int idx = cnt + rank;
                        sm.kbox[idx]    = sm.wbox[i];
                        sm.karea[idx]   = sm.warea[i];
                        sm.keepkey[idx] = sm.wkey[i];
                    }
                }
            }
        }
        __syncthreads();
        cnt = sm.cnt;
        if (sm.stop) break;
    }

    // ---- outputs [boxes 3200 | scores 800 | classes 800 | valid 800] ----
    if (tid < DETK) {
        int k = tid;
        float4 ob = make_float4(0.f, 0.f, 0.f, 0.f);
        float os = 0.f, oc = 0.f, ov = 0.f;
        if (k < cnt) {
            ob = sm.kbox[k];
            os = s2f(sm.keepkey[k]);
            oc = 1.0f;
            ov = 1.0f;
        }
        float* obp = out + ((size_t)b * DETK + k) * 4;
        obp[0] = ob.x; obp[1] = ob.y; obp[2] = ob.z; obp[3] = ob.w;
        const int SB = BN * DETK * 4;   // 3200
        const int SC = BN * DETK;       // 800
        out[SB +          b * DETK + k] = os;
        out[SB + SC +     b * DETK + k] = oc;
        out[SB + 2 * SC + b * DETK + k] = ov;
    }
}

extern "C" void kernel_launch(void* const* d_in, const int* in_sizes, int n_in,
                              void* d_out, int out_size) {
    const float* clss  = (const float*)d_in[0];
    const float* regs  = (const float*)d_in[1];
    const float* qlts  = (const float*)d_in[2];
    const float* props = (const float*)d_in[3];
    float* out = (float*)d_out;

    k1_decode_sort<<<BN * 4, NQ>>>(clss, regs, qlts, props);

    cudaLaunchConfig_t cfg = {};
    cfg.gridDim  = dim3(BN, 1, 1);
    cfg.blockDim = dim3(NT, 1, 1);
    cudaLaunchAttribute attrs[1];
    attrs[0].id = cudaLaunchAttributeProgrammaticStreamSerialization;
    attrs[0].val.programmaticStreamSerializationAllowed = 1;
    cfg.attrs    = attrs;
    cfg.numAttrs = 1;
    cudaLaunchKernelEx(&cfg, k2_merge_nms, (float*)d_out);
}